// round 17
// baseline (speedup 1.0000x reference)
#include <cuda_runtime.h>
#include <cuda_bf16.h>
#include <cstdint>

// ---------------------------------------------------------------------------
// Problem constants
// ---------------------------------------------------------------------------
#define NB   128
#define LL   64
#define HH   512
#define EE   512
#define NCELL 2080
#define CELLF 65536   // 128*512

typedef __nv_bfloat16 bf16;

// Tile config: task = 128(M) x 64(N), K full. 8 tasks per logical cell
// (one per 64-col N-slice). 8 warps: 2(m) x 4(n), warp tile 64x16.
// Precision: bf16 activations, fp32-pair weights: C = Ahi@Whi + Ahi@Wlo.
// K-chunk = 64 elements (128B rows).
#define RSB    144                // smem row stride bytes (128 data + 16 pad)
#define A_TILE_B (128 * RSB)      // 18432 bytes (A: 128 rows)
#define W_TILE_B (64 * RSB)       // 9216 bytes per W tile (64 rows)
#define STAGE_B (A_TILE_B + 2 * W_TILE_B)   // 36864
#define NSTAGE 3
#define GSMEM (NSTAGE * STAGE_B)  // 110592 dynamic (2 CTAs/SM -> 221KB)

#define NLCELL 2144               // 64 input + 2016 wave + 64 output
#define NTASK  (NLCELL * 8)
#define NCTA   296                // 2 per SM

// B-source dependency wait: issue(8) (first B chunk) happens at iter 6
// (depth-2 lookahead), so the wait must complete by then.
#define BDEP_CHUNK 6

// ---------------------------------------------------------------------------
// Device scratch (allocation-free)
// ---------------------------------------------------------------------------
__device__ bf16 g_Hhi[(size_t)NCELL * CELLF];    // 273 MB (activations, bf16)
__device__ bf16 g_Whi[HH * 2 * HH], g_Wlo[HH * 2 * HH];
__device__ bf16 g_WinHi[HH * EE],  g_WinLo[HH * EE];
__device__ bf16 g_WoutHi[EE * HH], g_WoutLo[EE * HH];
__device__ bf16 g_Xhi[8192 * EE];                // gathered embeddings (bf16)
__device__ float g_y[8192 * 512];
__device__ float g_part[NB];

// Scheduling state
__device__ int  g_next;
__device__ int  g_done[NCELL];        // completed tiles per cell; 8 = ready
__device__ int2 g_list[NLCELL];       // (s, k); k==0 input, k>0 wave, k==-1 output

__device__ __forceinline__ int cellidx(int s, int k) { return s * (s + 1) / 2 + k; }

__device__ __forceinline__ uint32_t smem_u32(const void* p) {
    uint32_t a;
    asm("{ .reg .u64 t; cvta.to.shared.u64 t, %1; cvt.u32.u64 %0, t; }" : "=r"(a) : "l"(p));
    return a;
}
__device__ __forceinline__ void cpa16(uint32_t dst, const void* src) {
    asm volatile("cp.async.ca.shared.global [%0], [%1], 16;" :: "r"(dst), "l"(src));
}
__device__ __forceinline__ void cp_commit() { asm volatile("cp.async.commit_group;" ::: "memory"); }
__device__ __forceinline__ void cp_wait1()  { asm volatile("cp.async.wait_group 1;" ::: "memory"); }
__device__ __forceinline__ void cp_wait0()  { asm volatile("cp.async.wait_group 0;" ::: "memory"); }

__device__ __forceinline__ int ld_acq(const int* p) {
    int v;
    asm volatile("ld.acquire.gpu.global.b32 %0, [%1];" : "=r"(v) : "l"(p));
    return v;
}
__device__ __forceinline__ void red_rel(int* p) {
    asm volatile("red.release.gpu.global.add.s32 [%0], 1;" :: "l"(p));
}

#define LDM4(r0, r1, r2, r3, addr) \
    asm volatile("ldmatrix.sync.aligned.m8n8.x4.shared.b16 {%0,%1,%2,%3}, [%4];" \
                 : "=r"(r0), "=r"(r1), "=r"(r2), "=r"(r3) : "r"(addr))

__device__ __forceinline__ void mma16816(float c[4], const uint32_t a[4], uint32_t b0, uint32_t b1) {
    asm volatile(
        "mma.sync.aligned.m16n8k16.row.col.f32.bf16.bf16.f32 "
        "{%0,%1,%2,%3},{%4,%5,%6,%7},{%8,%9},{%0,%1,%2,%3};"
        : "+f"(c[0]), "+f"(c[1]), "+f"(c[2]), "+f"(c[3])
        : "r"(a[0]), "r"(a[1]), "r"(a[2]), "r"(a[3]), "r"(b0), "r"(b1));
}

// ---------------------------------------------------------------------------
// Init: zero flags, reset counter, build interleaved topological cell list
// ---------------------------------------------------------------------------
__global__ void k_init()
{
    int i = blockIdx.x * blockDim.x + threadIdx.x;
    if (i < NCELL) g_done[i] = 0;
    if (i == 0) g_next = 0;
    if (i == 1) {
        int idx = 0;
        for (int s = 0; s < 64; ++s) g_list[idx++] = make_int2(s, 0);   // inputs
        g_list[idx++] = make_int2(0, -1);                               // output 0
        for (int d = 2; d <= 126; ++d) {
            int s_lo = (d + 1) / 2;
            if (d - 63 > s_lo) s_lo = d - 63;
            int s_hi = (d - 1 < 63) ? d - 1 : 63;
            for (int s = s_lo; s <= s_hi; ++s)
                g_list[idx++] = make_int2(s, d - s);                    // wave cells
            if ((d & 1) == 0)
                g_list[idx++] = make_int2(d / 2, -1);                   // output s=d/2
        }
    }
}

// ---------------------------------------------------------------------------
// Persistent SANI kernel: dependency-driven task loop over all GEMM tiles.
// Wave tasks wait on the A-source (diag d-2) up front; the critical B-source
// (diag d-1) wait is deferred to iter BDEP_CHUNK, just before issue(8).
// Pipeline: NSTAGE=3, depth-2 lookahead, issue AFTER the top-of-chunk barrier
// (stage (c+2)%3 == (c-1)%3 was fully consumed before that barrier).
// ---------------------------------------------------------------------------
__global__ void __launch_bounds__(256, 2)
k_sani(const float* __restrict__ b_in, const float* __restrict__ b_sani,
       const float* __restrict__ b_out)
{
    extern __shared__ __align__(128) char smem[];
    __shared__ int sh_task;

    const uint32_t sbase = smem_u32(smem);
    const int tid = threadIdx.x;
    const int wid = tid >> 5, lane = tid & 31;
    const int wm = wid & 1, wn = wid >> 1;       // warp grid 2(m) x 4(n)
    const int lr = lane >> 2;                    // 0..7
    const int lc2 = (lane & 3) * 2;              // 0,2,4,6

    // ldmatrix per-lane address components (byte offsets within a stage)
    const int arow = (lane & 7) + ((lane & 8) ? 8 : 0);
    const int akb  = (lane & 16) ? 16 : 0;       // second 8x8: k+8 -> +16B
    uint32_t aOff[4];
    #pragma unroll
    for (int mi = 0; mi < 4; ++mi)
        aOff[mi] = (uint32_t)((wm * 64 + mi * 16 + arow) * RSB) + akb;
    const int bnrow = wn * 16 + ((lane >> 4) & 1) * 8 + (lane & 7);
    const int bkb   = ((lane >> 3) & 1) * 16;
    const uint32_t bHiOff = (uint32_t)(A_TILE_B + bnrow * RSB) + bkb;
    const uint32_t bLoOff = (uint32_t)(A_TILE_B + W_TILE_B + bnrow * RSB) + bkb;

    for (;;) {
        if (tid == 0) sh_task = atomicAdd(&g_next, 1);
        __syncthreads();
        const int t = sh_task;
        __syncthreads();          // protect sh_task before next iteration's write
        if (t >= NTASK) return;

        const int lcell = t >> 3;
        const int n0 = (t & 7) * 64;             // N-slice base (0..448)

        const int2 cc = g_list[lcell];
        const int s = cc.x, k = cc.y;
        const int type = (k < 0) ? 2 : (k == 0 ? 0 : 1);

        // ---- up-front dependency wait (A-source / diagonal only) ----
        const int* pB = nullptr;                 // deferred B-source dep
        if (tid == 0) {
            if (type == 1) {
                const int* p1 = &g_done[cellidx(s - 1, k - 1)];
                while (ld_acq(p1) < 8) __nanosleep(64);
            } else if (type == 2) {
                const int* p = &g_done[cellidx(s, s)];
                while (ld_acq(p) < 8) __nanosleep(64);
            }
        }
        if (type == 1) pB = &g_done[cellidx(s, k - 1)];
        __syncthreads();

        // ---- operand pointers ----
        const bf16 *aH1, *aH2 = nullptr, *wH, *wL;
        const float* bias;
        int ldw, nch;
        if (type == 0) {
            aH1 = g_Xhi + (size_t)s * 128 * 512;
            wH = g_WinHi + (size_t)n0 * 512;  wL = g_WinLo + (size_t)n0 * 512;
            ldw = 512; nch = 8; bias = b_in;
        } else if (type == 1) {
            aH1 = g_Hhi + (size_t)cellidx(s - 1, k - 1) * CELLF;
            aH2 = g_Hhi + (size_t)cellidx(s,     k - 1) * CELLF;
            wH = g_Whi + (size_t)n0 * 1024;  wL = g_Wlo + (size_t)n0 * 1024;
            ldw = 1024; nch = 16; bias = b_sani;
        } else {
            aH1 = g_Hhi + (size_t)cellidx(s, s) * CELLF;
            wH = g_WoutHi + (size_t)n0 * 512;  wL = g_WoutLo + (size_t)n0 * 512;
            ldw = 512; nch = 8; bias = b_out;
        }

        // ---- GEMM: 128x64, K = nch*64, 2-product split ----
        float acc[4][2][4];
        #pragma unroll
        for (int i = 0; i < 4; ++i)
            #pragma unroll
            for (int j = 0; j < 2; ++j)
                #pragma unroll
                for (int q = 0; q < 4; ++q) acc[i][j][q] = 0.f;

        auto issue = [&](int c) {
            const bf16* ah; int ka;
            if (c < 8) { ah = aH1; ka = c * 64; }
            else       { ah = aH2; ka = (c - 8) * 64; }
            const int kw = c * 64;
            const uint32_t sm = sbase + (uint32_t)(c % NSTAGE) * STAGE_B;
            // A: 128 rows x 8 segs = 1024 transfers
            #pragma unroll
            for (int i = 0; i < 4; ++i) {
                const int ch = tid + i * 256;
                const int row = ch >> 3, seg = ch & 7;
                cpa16(sm + (uint32_t)(row * RSB + seg * 16),
                      ah + (size_t)row * 512 + ka + seg * 8);
            }
            // W hi/lo: 64 rows x 8 segs = 512 transfers each
            #pragma unroll
            for (int i = 0; i < 2; ++i) {
                const int ch = tid + i * 256;
                const int row = ch >> 3, seg = ch & 7;
                const uint32_t off = (uint32_t)(row * RSB + seg * 16);
                cpa16(sm + A_TILE_B + off,            wH + (size_t)row * ldw + kw + seg * 8);
                cpa16(sm + A_TILE_B + W_TILE_B + off, wL + (size_t)row * ldw + kw + seg * 8);
            }
            cp_commit();
        };

        issue(0); issue(1);

        for (int c = 0; c < nch; ++c) {
            if (c + 1 < nch) cp_wait1(); else cp_wait0();
            // Deferred B-source wait: must complete before issue(8) at iter 6.
            if (c == BDEP_CHUNK && pB && tid == 0)
                while (ld_acq(pB) < 8) __nanosleep(64);
            __syncthreads();      // all threads done with stage (c-1)%3; safe
                                  // to refill it below
            if (c + 2 < nch) issue(c + 2);

            const uint32_t stg = sbase + (uint32_t)(c % NSTAGE) * STAGE_B;
            #pragma unroll
            for (int ks = 0; ks < 4; ++ks) {
                const uint32_t kb = stg + ks * 32;   // 16 k-elements = 32 bytes
                uint32_t ah[4][4], bh[4], bl[4];
                LDM4(ah[0][0], ah[0][1], ah[0][2], ah[0][3], kb + aOff[0]);
                LDM4(ah[1][0], ah[1][1], ah[1][2], ah[1][3], kb + aOff[1]);
                LDM4(ah[2][0], ah[2][1], ah[2][2], ah[2][3], kb + aOff[2]);
                LDM4(ah[3][0], ah[3][1], ah[3][2], ah[3][3], kb + aOff[3]);
                LDM4(bh[0], bh[1], bh[2], bh[3], kb + bHiOff);
                LDM4(bl[0], bl[1], bl[2], bl[3], kb + bLoOff);
                // product-major: 8 independent accumulators between reuses
                #pragma unroll
                for (int mi = 0; mi < 4; ++mi)
                    #pragma unroll
                    for (int ni = 0; ni < 2; ++ni)
                        mma16816(acc[mi][ni], ah[mi], bh[ni * 2], bh[ni * 2 + 1]);
                #pragma unroll
                for (int mi = 0; mi < 4; ++mi)
                    #pragma unroll
                    for (int ni = 0; ni < 2; ++ni)
                        mma16816(acc[mi][ni], ah[mi], bl[ni * 2], bl[ni * 2 + 1]);
            }
        }

        // ---- epilogue ----
        int dstCell = (type == 0) ? cellidx(s, 0) : (type == 1 ? cellidx(s, k) : -1);
        bf16* outHi = (dstCell >= 0) ? g_Hhi + (size_t)dstCell * CELLF : nullptr;
        float* outF = (type == 2) ? g_y + (size_t)s * 128 * 512 : nullptr;

        #pragma unroll
        for (int mi = 0; mi < 4; ++mi) {
            const int r0 = wm * 64 + mi * 16 + lr;             // row within 128
            #pragma unroll
            for (int ni = 0; ni < 2; ++ni) {
                const int ccol = n0 + wn * 16 + ni * 8 + lc2;
                const float bx = bias[ccol];
                const float by = bias[ccol + 1];
                #pragma unroll
                for (int half = 0; half < 2; ++half) {
                    const int r = r0 + half * 8;
                    const float v0 = acc[mi][ni][half * 2]     + bx;
                    const float v1 = acc[mi][ni][half * 2 + 1] + by;
                    if (outF) {
                        float2 fv; fv.x = v0; fv.y = v1;
                        *reinterpret_cast<float2*>(outF + (size_t)r * 512 + ccol) = fv;
                    } else {
                        __nv_bfloat162 hp;
                        hp.x = __float2bfloat16(v0);
                        hp.y = __float2bfloat16(v1);
                        *reinterpret_cast<__nv_bfloat162*>(outHi + (size_t)r * 512 + ccol) = hp;
                    }
                }
            }
        }

        // ---- signal completion (per cell) ----
        if (dstCell >= 0) {
            __threadfence();
            __syncthreads();
            if (tid == 0) red_rel(&g_done[dstCell]);
        }
    }
}

// ---------------------------------------------------------------------------
// Prep kernels (weights split to fp32-pair; activations bf16 only)
// ---------------------------------------------------------------------------
__global__ void k_split_sani(const float* __restrict__ src) {
    int i = blockIdx.x * blockDim.x + threadIdx.x;
    float v = src[i];
    bf16 h = __float2bfloat16(v);
    g_Whi[i] = h;
    g_Wlo[i] = __float2bfloat16(v - __bfloat162float(h));
}
__global__ void k_split_in(const float* __restrict__ src) {
    int i = blockIdx.x * blockDim.x + threadIdx.x;
    float v = src[i];
    bf16 h = __float2bfloat16(v);
    g_WinHi[i] = h;
    g_WinLo[i] = __float2bfloat16(v - __bfloat162float(h));
}
__global__ void k_split_out(const float* __restrict__ src) {
    int i = blockIdx.x * blockDim.x + threadIdx.x;
    float v = src[i];
    bf16 h = __float2bfloat16(v);
    g_WoutHi[i] = h;
    g_WoutLo[i] = __float2bfloat16(v - __bfloat162float(h));
}

__global__ void __launch_bounds__(256)
k_gather(const int* __restrict__ labels, const float* __restrict__ emb)
{
    const int r = blockIdx.x;            // r = s*128 + n
    const int n = r & 127, s = r >> 7;
    const float* row = emb + (size_t)labels[n * LL + s] * EE;
    const int e = threadIdx.x * 2;
    float2 v = *reinterpret_cast<const float2*>(row + e);
    __nv_bfloat162 hp;
    hp.x = __float2bfloat16(v.x);
    hp.y = __float2bfloat16(v.y);
    *reinterpret_cast<__nv_bfloat162*>(g_Xhi + (size_t)r * EE + e) = hp;
}

// ---------------------------------------------------------------------------
// Loss (flat row r = s*128+n; reshape(N,L,E) reads flat row n*64+l)
// ---------------------------------------------------------------------------
__global__ void __launch_bounds__(512)
k_loss(const int* __restrict__ labels, const float* __restrict__ emb_table)
{
    __shared__ float red[512];
    const int n = blockIdx.x;
    const int e = threadIdx.x;
    const float* yb = g_y + (size_t)n * LL * EE + e;

    float m = -1e30f;
    #pragma unroll
    for (int l = 0; l < LL; ++l) m = fmaxf(m, yb[(size_t)l * EE]);

    float se = 0.f, dot = 0.f, sume = 0.f;
    #pragma unroll
    for (int l = 0; l < LL; ++l) {
        float yv = yb[(size_t)l * EE];
        float ev = emb_table[(size_t)labels[n * LL + l] * EE + e];
        se   += expf(yv - m);
        dot  += ev * yv;
        sume += ev;
    }
    float lse = m + logf(se);
    red[e] = dot - sume * lse;
    __syncthreads();
    for (int stride = 256; stride > 0; stride >>= 1) {
        if (e < stride) red[e] += red[e + stride];
        __syncthreads();
    }
    if (e == 0) g_part[n] = red[0];
}

__global__ void k_final(float* __restrict__ out)
{
    __shared__ float red[128];
    const int t = threadIdx.x;
    red[t] = g_part[t];
    __syncthreads();
    for (int stride = 64; stride > 0; stride >>= 1) {
        if (t < stride) red[t] += red[t + stride];
        __syncthreads();
    }
    if (t == 0) out[0] = -red[0] / (float)(NB * EE);
}

// ---------------------------------------------------------------------------
extern "C" void kernel_launch(void* const* d_in, const int* in_sizes, int n_in,
                              void* d_out, int out_size)
{
    const int*   labels    = (const int*)  d_in[0];
    const float* emb_table = (const float*)d_in[1];
    const float* W_in      = (const float*)d_in[2];
    const float* b_in      = (const float*)d_in[3];
    const float* W_sani    = (const float*)d_in[4];
    const float* b_sani    = (const float*)d_in[5];
    const float* W_out     = (const float*)d_in[6];
    const float* b_out     = (const float*)d_in[7];

    // Unconditional each call (no static guards; idempotent non-stream API)
    cudaFuncSetAttribute(k_sani, cudaFuncAttributeMaxDynamicSharedMemorySize, GSMEM);

    // Scheduling state reset + task list build
    k_init<<<17, 256>>>();

    // Weight splits + embedding gather
    k_split_sani<<<2048, 256>>>(W_sani);
    k_split_in<<<1024, 256>>>(W_in);
    k_split_out<<<1024, 256>>>(W_out);
    k_gather<<<8192, 256>>>(labels, emb_table);

    // All GEMM work: one persistent dependency-driven kernel (2 CTAs/SM)
    k_sani<<<NCTA, 256, GSMEM>>>(b_in, b_sani, b_out);

    // Loss
    k_loss<<<NB, 512>>>(labels, emb_table);
    k_final<<<1, 128>>>((float*)d_out);
}